// round 14
// baseline (speedup 1.0000x reference)
#include <cuda_runtime.h>
#include <cuda_bf16.h>
#include <mma.h>
#include <math.h>
#include <stdint.h>

using namespace nvcuda;

#define NJ 24
#define POSE_STRIDE (NJ * 3)
#define GROW 12
#define MAX_B 1024
#define MAX_ROWS (4 * MAX_B)      // 4 rows per batch (x=0..2 real, x=3 zero pad)
#define MAX_VPAD 8192
#define SEC 97                    // real K per split-section
#define KTOT 320                  // 3*97=291 padded to 320
#define KC 32                     // K per pipeline chunk
#define NCHUNK (KTOT / KC)        // 10
#define LDS 40                    // SMEM leading dim (bf16), 80B rows

__constant__ int c_par[NJ] = {-1, 0, 0, 0, 1, 2, 3, 4, 5, 6, 7, 8, 9, 9, 9,
                              12, 13, 14, 16, 17, 18, 19, 20, 21};

// scratch (no allocation)
__device__ float g_G[MAX_B * NJ * GROW];
__device__ __align__(256) __nv_bfloat16 g_A[(size_t)MAX_ROWS * KTOT];
__device__ __align__(256) __nv_bfloat16 g_Bm[(size_t)MAX_VPAD * KTOT];

__device__ __forceinline__ uint32_t smem_u32(const void* p) {
    uint32_t a;
    asm("{ .reg .u64 t; cvta.to.shared.u64 t, %1; cvt.u32.u64 %0, t; }"
        : "=r"(a) : "l"(p));
    return a;
}
__device__ __forceinline__ void cp_async16(uint32_t dst, const void* src) {
    asm volatile("cp.async.cg.shared.global [%0], [%1], 16;"
                 :: "r"(dst), "l"(src) : "memory");
}
__device__ __forceinline__ void cp_commit() {
    asm volatile("cp.async.commit_group;" ::: "memory");
}
__device__ __forceinline__ void cp_wait1() {
    asm volatile("cp.async.wait_group 1;" ::: "memory");
}
__device__ __forceinline__ void cp_wait0() {
    asm volatile("cp.async.wait_group 0;" ::: "memory");
}

// ---------------------------------------------------------------------------
// Kernel 1: forward kinematics (correctness-proven).
// ---------------------------------------------------------------------------
__global__ void fk_kernel(const float* __restrict__ pose,
                          const float* __restrict__ J_hat, int B) {
    int b = blockIdx.x;
    if (b >= B) return;
    __shared__ float Gs[NJ][GROW];
    int t = threadIdx.x;
    if (t < NJ) {
        float rx = pose[b * POSE_STRIDE + t * 3 + 0];
        float ry = pose[b * POSE_STRIDE + t * 3 + 1];
        float rz = pose[b * POSE_STRIDE + t * 3 + 2];
        float theta = sqrtf(rx * rx + ry * ry + rz * rz) + 1e-8f;
        float inv = 1.0f / theta;
        float ux = rx * inv, uy = ry * inv, uz = rz * inv;
        float c = cosf(theta), s = sinf(theta), ic = 1.0f - c;
        int p = c_par[t];
        float jx = J_hat[t * 3 + 0], jy = J_hat[t * 3 + 1], jz = J_hat[t * 3 + 2];
        if (p >= 0) { jx -= J_hat[p*3+0]; jy -= J_hat[p*3+1]; jz -= J_hat[p*3+2]; }
        Gs[t][0] = c + ic*ux*ux;  Gs[t][1] = ic*ux*uy - s*uz; Gs[t][2]  = ic*ux*uz + s*uy; Gs[t][3]  = jx;
        Gs[t][4] = ic*uy*ux+s*uz; Gs[t][5] = c + ic*uy*uy;    Gs[t][6]  = ic*uy*uz - s*ux; Gs[t][7]  = jy;
        Gs[t][8] = ic*uz*ux-s*uy; Gs[t][9] = ic*uz*uy + s*ux; Gs[t][10] = c + ic*uz*uz;    Gs[t][11] = jz;
    }
    __syncthreads();
    if (t == 0) {
        for (int i = 1; i < NJ; i++) {
            int p = c_par[i];
            float tmp[GROW];
            #pragma unroll
            for (int x = 0; x < 3; x++) {
                float p0 = Gs[p][x*4+0], p1 = Gs[p][x*4+1], p2 = Gs[p][x*4+2], p3 = Gs[p][x*4+3];
                tmp[x*4+0] = p0*Gs[i][0] + p1*Gs[i][4] + p2*Gs[i][8];
                tmp[x*4+1] = p0*Gs[i][1] + p1*Gs[i][5] + p2*Gs[i][9];
                tmp[x*4+2] = p0*Gs[i][2] + p1*Gs[i][6] + p2*Gs[i][10];
                tmp[x*4+3] = p0*Gs[i][3] + p1*Gs[i][7] + p2*Gs[i][11] + p3;
            }
            #pragma unroll
            for (int k = 0; k < GROW; k++) Gs[i][k] = tmp[k];
        }
    }
    __syncthreads();
    if (t < NJ) {
        float jx = J_hat[t*3+0], jy = J_hat[t*3+1], jz = J_hat[t*3+2];
        Gs[t][3]  -= Gs[t][0]*jx + Gs[t][1]*jy + Gs[t][2]*jz;
        Gs[t][7]  -= Gs[t][4]*jx + Gs[t][5]*jy + Gs[t][6]*jz;
        Gs[t][11] -= Gs[t][8]*jx + Gs[t][9]*jy + Gs[t][10]*jz;
    }
    __syncthreads();
    const float* src = &Gs[0][0];
    float* dst = g_G + (size_t)b * NJ * GROW;
    for (int i = t; i < NJ * GROW; i += blockDim.x) dst[i] = src[i];
}

// ---------------------------------------------------------------------------
// prep_all: blocks [0, rows_pad) build A rows; [rows_pad, rows_pad+vpad) build
// B rows. A sections [Ah|Ah|Al], B sections [Bh|Bl|Bh] at K offsets 0/97/194;
// zeros at 291..319.
// ---------------------------------------------------------------------------
__global__ void prep_all(const float* __restrict__ trans,
                         const float* __restrict__ T_hat,
                         const float* __restrict__ W,
                         int B, int V, int rows_pad) {
    int blk = blockIdx.x;
    int k = threadIdx.x;                 // 0..127
    if (blk < rows_pad) {
        int row = blk;
        int b = row >> 2, x = row & 3;
        __nv_bfloat16* r = g_A + (size_t)row * KTOT;
        if (k < SEC) {
            float val = 0.0f;
            if (b < B && x < 3) {
                if (k < 96) {
                    int j = k >> 2, y = k & 3;
                    val = g_G[(size_t)b * NJ * GROW + j * GROW + x * 4 + y];
                } else {
                    val = trans[b * 3 + x];
                }
            }
            __nv_bfloat16 hi = __float2bfloat16(val);
            __nv_bfloat16 lo = __float2bfloat16(val - __bfloat162float(hi));
            r[k] = hi; r[SEC + k] = hi; r[2 * SEC + k] = lo;
        } else if (2 * SEC + k < KTOT) {
            r[2 * SEC + k] = __float2bfloat16(0.0f);
        }
    } else {
        int v = blk - rows_pad;
        __nv_bfloat16* r = g_Bm + (size_t)v * KTOT;
        if (k < SEC) {
            float val = 0.0f;
            if (v < V) {
                if (k < 96) {
                    int j = k >> 2, y = k & 3;
                    float vh = (y < 3) ? T_hat[v * 3 + y] : 1.0f;
                    val = W[(size_t)v * NJ + j] * vh;
                } else {
                    val = 1.0f;
                }
            }
            __nv_bfloat16 hi = __float2bfloat16(val);
            __nv_bfloat16 lo = __float2bfloat16(val - __bfloat162float(hi));
            r[k] = hi; r[SEC + k] = lo; r[2 * SEC + k] = hi;
        } else if (2 * SEC + k < KTOT) {
            r[2 * SEC + k] = __float2bfloat16(0.0f);
        }
    }
}

// ---------------------------------------------------------------------------
// GEMM via wmma bf16, double-buffered cp.async pipeline over K chunks.
// CTA: 256 thr = 8 warps (4 row x 2 col); warp tile 32x64; CTA tile 128x128.
// ---------------------------------------------------------------------------
#define LDC 68                     // epilogue stage: 128 x (64+4) floats
#define TILE_ELEMS (128 * LDS)     // 5120 bf16 per tile
#define BUF_ELEMS (2 * TILE_ELEMS) // A+B per buffer

__global__ __launch_bounds__(256)
void gemm_kernel(float* __restrict__ out, int V, int B) {
    // stage: 2 buffers x (A tile + B tile) = 40960 B; epilogue (34816 B) unions
    __shared__ __align__(16) __nv_bfloat16 smbuf[2 * BUF_ELEMS];
    float* sepi = reinterpret_cast<float*>(smbuf);

    int tid = threadIdx.x;
    int warp = tid >> 5;
    int wr = warp >> 1;                  // 0..3 row-warp
    int wc = warp & 1;                   // 0..1 col-warp
    int r0 = blockIdx.x * 128;
    int v0 = blockIdx.y * 128;

    wmma::fragment<wmma::accumulator, 16, 16, 16, float> acc[2][4];
    #pragma unroll
    for (int i = 0; i < 2; i++)
        #pragma unroll
        for (int j = 0; j < 4; j++)
            wmma::fill_fragment(acc[i][j], 0.0f);

    uint32_t sbase = smem_u32(smbuf);

    // stage one KC-chunk (A+B) into buffer `buf`: 128 rows x 32 bf16 = 4 segs
    auto stage = [&](int c, int buf) {
        uint32_t dst = sbase + (uint32_t)buf * BUF_ELEMS * 2;
        #pragma unroll
        for (int p = 0; p < 2; p++) {
            int idx = p * 256 + tid;           // 0..511
            int row = idx >> 2, seg = idx & 3;
            uint32_t soff = (uint32_t)(row * LDS + seg * 8) * 2;
            cp_async16(dst + soff,
                       g_A + (size_t)(r0 + row) * KTOT + c * KC + seg * 8);
            cp_async16(dst + TILE_ELEMS * 2 + soff,
                       g_Bm + (size_t)(v0 + row) * KTOT + c * KC + seg * 8);
        }
        cp_commit();
    };

    stage(0, 0);
    for (int c = 0; c < NCHUNK; c++) {
        if (c + 1 < NCHUNK) {
            stage(c + 1, (c + 1) & 1);
            cp_wait1();
        } else {
            cp_wait0();
        }
        __syncthreads();

        const __nv_bfloat16* sA = smbuf + (size_t)(c & 1) * BUF_ELEMS;
        const __nv_bfloat16* sB = sA + TILE_ELEMS;
        #pragma unroll
        for (int ks = 0; ks < KC / 16; ks++) {
            int kk = ks * 16;
            wmma::fragment<wmma::matrix_a, 16, 16, 16, __nv_bfloat16, wmma::row_major> af[2];
            wmma::fragment<wmma::matrix_b, 16, 16, 16, __nv_bfloat16, wmma::col_major> bf[4];
            #pragma unroll
            for (int i = 0; i < 2; i++)
                wmma::load_matrix_sync(af[i], sA + (wr * 32 + i * 16) * LDS + kk, LDS);
            #pragma unroll
            for (int j = 0; j < 4; j++)
                wmma::load_matrix_sync(bf[j], sB + (wc * 64 + j * 16) * LDS + kk, LDS);
            #pragma unroll
            for (int i = 0; i < 2; i++)
                #pragma unroll
                for (int j = 0; j < 4; j++)
                    wmma::mma_sync(acc[i][j], af[i], bf[j], acc[i][j]);
        }
        __syncthreads();
    }

    // Epilogue: two passes (col-warp halves) through SMEM, coalesced float3 out.
    int b_base = r0 >> 2;
    for (int p = 0; p < 2; p++) {
        __syncthreads();
        if (wc == p) {
            #pragma unroll
            for (int i = 0; i < 2; i++)
                #pragma unroll
                for (int j = 0; j < 4; j++)
                    wmma::store_matrix_sync(sepi + (wr * 32 + i * 16) * LDC + j * 16,
                                            acc[i][j], LDC, wmma::mem_row_major);
        }
        __syncthreads();

        #pragma unroll
        for (int idx = tid; idx < 32 * 64; idx += 256) {
            int bl = idx >> 6;
            int vl = idx & 63;
            int b = b_base + bl;
            int v = v0 + p * 64 + vl;
            if (b < B && v < V) {
                const float* srow = sepi + (4 * bl) * LDC + vl;
                float* o = out + ((size_t)b * V + v) * 3;
                o[0] = srow[0 * LDC];
                o[1] = srow[1 * LDC];
                o[2] = srow[2 * LDC];
            }
        }
    }
}

// ---------------------------------------------------------------------------
// Launch: pure kernel launches only (graph-capture safe).
// ---------------------------------------------------------------------------
extern "C" void kernel_launch(void* const* d_in, const int* in_sizes, int n_in,
                              void* d_out, int out_size) {
    const float* T_hat   = (const float*)d_in[0];   // (V,3)
    const float* J_hat   = (const float*)d_in[1];   // (24,3)
    const float* weights = (const float*)d_in[2];   // (V,24)
    const float* pose    = (const float*)d_in[3];   // (B,72)
    const float* trans   = (const float*)d_in[4];   // (B,3)
    float* out = (float*)d_out;

    int V = in_sizes[0] / 3;
    int B = in_sizes[3] / POSE_STRIDE;
    if (B > MAX_B) B = MAX_B;

    int rows_pad = ((4 * B + 127) / 128) * 128;     // 2048 for B=512
    int vpad = ((V + 127) / 128) * 128;             // 6912 for V=6890
    if (rows_pad > MAX_ROWS) rows_pad = MAX_ROWS;
    if (vpad > MAX_VPAD) vpad = MAX_VPAD;

    fk_kernel<<<B, 32>>>(pose, J_hat, B);
    prep_all<<<rows_pad + vpad, 128>>>(trans, T_hat, weights, B, V, rows_pad);

    dim3 grid(rows_pad / 128, vpad / 128);
    gemm_kernel<<<grid, 256>>>(out, V, B);
}

// round 15
// speedup vs baseline: 1.0291x; 1.0291x over previous
#include <cuda_runtime.h>
#include <cuda_bf16.h>
#include <mma.h>
#include <math.h>
#include <stdint.h>

using namespace nvcuda;

#define NJ 24
#define POSE_STRIDE (NJ * 3)
#define GROW 12
#define MAX_B 1024
#define MAX_ROWS (4 * MAX_B)
#define MAX_VPAD 8192
#define SEC 97                    // real K per split-section
#define KTOT 320                  // 3*97=291 padded to 320
#define KC 64                     // K per smem chunk (serialized loop — proven)
#define NCHUNK (KTOT / KC)        // 5
#define LDS 72                    // SMEM leading dim (bf16), 144B rows

__constant__ int c_par[NJ] = {-1, 0, 0, 0, 1, 2, 3, 4, 5, 6, 7, 8, 9, 9, 9,
                              12, 13, 14, 16, 17, 18, 19, 20, 21};
// tree level of each joint (root=0, max depth 8)
__constant__ int c_lvl[NJ] = {0, 1, 1, 1, 2, 2, 2, 3, 3, 3, 4, 4, 4, 4, 4,
                              5, 5, 5, 6, 6, 7, 7, 8, 8};

// scratch (no allocation)
__device__ __align__(256) __nv_bfloat16 g_A[(size_t)MAX_ROWS * KTOT];
__device__ __align__(256) __nv_bfloat16 g_Bm[(size_t)MAX_VPAD * KTOT];

__device__ __forceinline__ uint32_t smem_u32(const void* p) {
    uint32_t a;
    asm("{ .reg .u64 t; cvta.to.shared.u64 t, %1; cvt.u32.u64 %0, t; }"
        : "=r"(a) : "l"(p));
    return a;
}
__device__ __forceinline__ void cp_async16(uint32_t dst, const void* src) {
    asm volatile("cp.async.cg.shared.global [%0], [%1], 16;"
                 :: "r"(dst), "l"(src) : "memory");
}
__device__ __forceinline__ void cp_async_wait_all() {
    asm volatile("cp.async.commit_group;\n\tcp.async.wait_group 0;" ::: "memory");
}

// ---------------------------------------------------------------------------
// fkA_kernel: one block per batch. Level-parallel FK (9 barrier steps instead
// of a 23-step serial chain), then emits the batch's 3 GEMM A-rows directly
// (split-bf16 sections [Ah|Ah|Al] at K offsets 0/97/194, zeros to 320).
// ---------------------------------------------------------------------------
__global__ __launch_bounds__(128)
void fkA_kernel(const float* __restrict__ pose,
                const float* __restrict__ J_hat,
                const float* __restrict__ trans, int B) {
    int b = blockIdx.x;
    if (b >= B) return;
    __shared__ float Gs[NJ][GROW];
    int t = threadIdx.x;

    if (t < NJ) {
        float rx = pose[b * POSE_STRIDE + t * 3 + 0];
        float ry = pose[b * POSE_STRIDE + t * 3 + 1];
        float rz = pose[b * POSE_STRIDE + t * 3 + 2];
        float theta = sqrtf(rx * rx + ry * ry + rz * rz) + 1e-8f;
        float inv = 1.0f / theta;
        float ux = rx * inv, uy = ry * inv, uz = rz * inv;
        float c = cosf(theta), s = sinf(theta), ic = 1.0f - c;
        int p = c_par[t];
        float jx = J_hat[t * 3 + 0], jy = J_hat[t * 3 + 1], jz = J_hat[t * 3 + 2];
        if (p >= 0) { jx -= J_hat[p*3+0]; jy -= J_hat[p*3+1]; jz -= J_hat[p*3+2]; }
        Gs[t][0] = c + ic*ux*ux;  Gs[t][1] = ic*ux*uy - s*uz; Gs[t][2]  = ic*ux*uz + s*uy; Gs[t][3]  = jx;
        Gs[t][4] = ic*uy*ux+s*uz; Gs[t][5] = c + ic*uy*uy;    Gs[t][6]  = ic*uy*uz - s*ux; Gs[t][7]  = jy;
        Gs[t][8] = ic*uz*ux-s*uy; Gs[t][9] = ic*uz*uy + s*ux; Gs[t][10] = c + ic*uz*uz;    Gs[t][11] = jz;
    }
    __syncthreads();

    // level-parallel compose: at level lv every joint multiplies its finalized
    // parent transform by its local transform.
    int mylvl = (t < NJ) ? c_lvl[t] : -1;
    int myp = (t < NJ) ? c_par[t] : -1;
    #pragma unroll
    for (int lv = 1; lv <= 8; lv++) {
        float tmp[GROW];
        bool act = (mylvl == lv);
        if (act) {
            #pragma unroll
            for (int x = 0; x < 3; x++) {
                float p0 = Gs[myp][x*4+0], p1 = Gs[myp][x*4+1];
                float p2 = Gs[myp][x*4+2], p3 = Gs[myp][x*4+3];
                tmp[x*4+0] = p0*Gs[t][0] + p1*Gs[t][4] + p2*Gs[t][8];
                tmp[x*4+1] = p0*Gs[t][1] + p1*Gs[t][5] + p2*Gs[t][9];
                tmp[x*4+2] = p0*Gs[t][2] + p1*Gs[t][6] + p2*Gs[t][10];
                tmp[x*4+3] = p0*Gs[t][3] + p1*Gs[t][7] + p2*Gs[t][11] + p3;
            }
        }
        __syncthreads();
        if (act) {
            #pragma unroll
            for (int k = 0; k < GROW; k++) Gs[t][k] = tmp[k];
        }
        __syncthreads();
    }

    if (t < NJ) {
        float jx = J_hat[t*3+0], jy = J_hat[t*3+1], jz = J_hat[t*3+2];
        Gs[t][3]  -= Gs[t][0]*jx + Gs[t][1]*jy + Gs[t][2]*jz;
        Gs[t][7]  -= Gs[t][4]*jx + Gs[t][5]*jy + Gs[t][6]*jz;
        Gs[t][11] -= Gs[t][8]*jx + Gs[t][9]*jy + Gs[t][10]*jz;
    }
    __syncthreads();

    // emit 3 A-rows (row = 3b + x), K cols 0..96 real, sections 0/97/194.
    for (int idx = t; idx < 3 * SEC; idx += 128) {
        int x = idx / SEC, k = idx - x * SEC;
        float val;
        if (k < 96) {
            int j = k >> 2, y = k & 3;
            val = Gs[j][x * 4 + y];
        } else {
            val = trans[b * 3 + x];
        }
        __nv_bfloat16 hi = __float2bfloat16(val);
        __nv_bfloat16 lo = __float2bfloat16(val - __bfloat162float(hi));
        __nv_bfloat16* r = g_A + (size_t)(3 * b + x) * KTOT;
        r[k] = hi; r[SEC + k] = hi; r[2 * SEC + k] = lo;
    }
    // zero K padding cols 291..319 on all 3 rows
    for (int idx = t; idx < 3 * (KTOT - 3 * SEC); idx += 128) {
        int x = idx / (KTOT - 3 * SEC), k = idx - x * (KTOT - 3 * SEC);
        g_A[(size_t)(3 * b + x) * KTOT + 3 * SEC + k] = __float2bfloat16(0.0f);
    }
}

// ---------------------------------------------------------------------------
// prep_B: one block per padded vertex. Sections [Bh|Bl|Bh] at 0/97/194.
// m[4j+y] = w[v,j]*vh[v,y]; k=96 -> 1.
// ---------------------------------------------------------------------------
__global__ void prep_B(const float* __restrict__ T_hat,
                       const float* __restrict__ W, int V) {
    int v = blockIdx.x;
    int k = threadIdx.x;                 // 0..127
    __nv_bfloat16* r = g_Bm + (size_t)v * KTOT;
    if (k < SEC) {
        float val = 0.0f;
        if (v < V) {
            if (k < 96) {
                int j = k >> 2, y = k & 3;
                float vh = (y < 3) ? T_hat[v * 3 + y] : 1.0f;
                val = W[(size_t)v * NJ + j] * vh;
            } else {
                val = 1.0f;
            }
        }
        __nv_bfloat16 hi = __float2bfloat16(val);
        __nv_bfloat16 lo = __float2bfloat16(val - __bfloat162float(hi));
        r[k] = hi; r[SEC + k] = lo; r[2 * SEC + k] = hi;
    } else if (2 * SEC + k < KTOT) {
        r[2 * SEC + k] = __float2bfloat16(0.0f);
    }
}

// ---------------------------------------------------------------------------
// GEMM via wmma bf16, SMEM-staged KC=64 chunks (proven 48us structure),
// M=3B rows (no pad rows). CTA tile 128x128; 8 warps (4 row x 2 col).
// ---------------------------------------------------------------------------
#define LDC 68     // epilogue stage: 128 x (64+4) floats

__global__ __launch_bounds__(256)
void gemm_kernel(float* __restrict__ out, int V, int B) {
    __shared__ __align__(16) char smbuf[2 * 128 * LDS * 2];  // 36.9 KB
    __nv_bfloat16* sA = reinterpret_cast<__nv_bfloat16*>(smbuf);
    __nv_bfloat16* sB = sA + 128 * LDS;
    float* sepi = reinterpret_cast<float*>(smbuf);

    int tid = threadIdx.x;
    int warp = tid >> 5;
    int wr = warp >> 1;
    int wc = warp & 1;
    int r0 = blockIdx.x * 128;
    int v0 = blockIdx.y * 128;
    int M = 3 * B;

    wmma::fragment<wmma::accumulator, 16, 16, 16, float> acc[2][4];
    #pragma unroll
    for (int i = 0; i < 2; i++)
        #pragma unroll
        for (int j = 0; j < 4; j++)
            wmma::fill_fragment(acc[i][j], 0.0f);

    uint32_t sA32 = smem_u32(sA);
    uint32_t sB32 = smem_u32(sB);

    for (int c = 0; c < NCHUNK; c++) {
        #pragma unroll
        for (int p = 0; p < 4; p++) {
            int idx = p * 256 + tid;             // 0..1023
            int row = idx >> 3, seg = idx & 7;
            uint32_t soff = (uint32_t)(row * LDS + seg * 8) * 2;
            cp_async16(sA32 + soff,
                       g_A + (size_t)(r0 + row) * KTOT + c * KC + seg * 8);
            cp_async16(sB32 + soff,
                       g_Bm + (size_t)(v0 + row) * KTOT + c * KC + seg * 8);
        }
        cp_async_wait_all();
        __syncthreads();

        #pragma unroll
        for (int ks = 0; ks < KC / 16; ks++) {
            int kk = ks * 16;
            wmma::fragment<wmma::matrix_a, 16, 16, 16, __nv_bfloat16, wmma::row_major> af[2];
            wmma::fragment<wmma::matrix_b, 16, 16, 16, __nv_bfloat16, wmma::col_major> bf[4];
            #pragma unroll
            for (int i = 0; i < 2; i++)
                wmma::load_matrix_sync(af[i], sA + (wr * 32 + i * 16) * LDS + kk, LDS);
            #pragma unroll
            for (int j = 0; j < 4; j++)
                wmma::load_matrix_sync(bf[j], sB + (wc * 64 + j * 16) * LDS + kk, LDS);
            #pragma unroll
            for (int i = 0; i < 2; i++)
                #pragma unroll
                for (int j = 0; j < 4; j++)
                    wmma::mma_sync(acc[i][j], af[i], bf[j], acc[i][j]);
        }
        __syncthreads();
    }

    // Epilogue: two passes (col-warp halves) through SMEM; row -> (b, x) by /3.
    for (int p = 0; p < 2; p++) {
        __syncthreads();
        if (wc == p) {
            #pragma unroll
            for (int i = 0; i < 2; i++)
                #pragma unroll
                for (int j = 0; j < 4; j++)
                    wmma::store_matrix_sync(sepi + (wr * 32 + i * 16) * LDC + j * 16,
                                            acc[i][j], LDC, wmma::mem_row_major);
        }
        __syncthreads();

        #pragma unroll 4
        for (int idx = tid; idx < 128 * 64; idx += 256) {
            int row = idx >> 6;
            int vl = idx & 63;
            int gr = r0 + row;
            int v = v0 + p * 64 + vl;
            if (gr < M && v < V) {
                int b = gr / 3;
                int x = gr - 3 * b;
                out[((size_t)b * V + v) * 3 + x] = sepi[row * LDC + vl];
            }
        }
    }
}

// ---------------------------------------------------------------------------
// Launch: pure kernel launches only (graph-capture safe).
// ---------------------------------------------------------------------------
extern "C" void kernel_launch(void* const* d_in, const int* in_sizes, int n_in,
                              void* d_out, int out_size) {
    const float* T_hat   = (const float*)d_in[0];   // (V,3)
    const float* J_hat   = (const float*)d_in[1];   // (24,3)
    const float* weights = (const float*)d_in[2];   // (V,24)
    const float* pose    = (const float*)d_in[3];   // (B,72)
    const float* trans   = (const float*)d_in[4];   // (B,3)
    float* out = (float*)d_out;

    int V = in_sizes[0] / 3;
    int B = in_sizes[3] / POSE_STRIDE;
    if (B > MAX_B) B = MAX_B;

    int rows_pad = ((3 * B + 127) / 128) * 128;     // 1536 for B=512 (exact)
    int vpad = ((V + 127) / 128) * 128;             // 6912 for V=6890
    if (rows_pad > MAX_ROWS) rows_pad = MAX_ROWS;
    if (vpad > MAX_VPAD) vpad = MAX_VPAD;

    fkA_kernel<<<B, 128>>>(pose, J_hat, trans, B);
    prep_B<<<vpad, 128>>>(T_hat, weights, V);

    dim3 grid(rows_pad / 128, vpad / 128);
    gemm_kernel<<<grid, 256>>>(out, V, B);
}

// round 16
// speedup vs baseline: 1.6963x; 1.6484x over previous
#include <cuda_runtime.h>
#include <cuda_fp16.h>
#include <mma.h>
#include <math.h>
#include <stdint.h>

using namespace nvcuda;

#define NJ 24
#define POSE_STRIDE (NJ * 3)
#define GROW 12
#define MAX_B 1024
#define MAX_ROWS (4 * MAX_B)
#define MAX_VPAD 8192
#define KREAL 97                  // 96 G-cols + 1 trans col
#define KTOT 128                  // padded K (single fp16 pass, no split)
#define KC 64                     // K per smem chunk
#define NCHUNK (KTOT / KC)        // 2
#define LDS 72                    // SMEM leading dim (fp16), 144B rows

__constant__ int c_par[NJ] = {-1, 0, 0, 0, 1, 2, 3, 4, 5, 6, 7, 8, 9, 9, 9,
                              12, 13, 14, 16, 17, 18, 19, 20, 21};
// tree level of each joint (root=0, max depth 8)
__constant__ int c_lvl[NJ] = {0, 1, 1, 1, 2, 2, 2, 3, 3, 3, 4, 4, 4, 4, 4,
                              5, 5, 5, 6, 6, 7, 7, 8, 8};

// scratch (no allocation)
__device__ __align__(256) __half g_A[(size_t)MAX_ROWS * KTOT];
__device__ __align__(256) __half g_Bm[(size_t)MAX_VPAD * KTOT];

__device__ __forceinline__ uint32_t smem_u32(const void* p) {
    uint32_t a;
    asm("{ .reg .u64 t; cvta.to.shared.u64 t, %1; cvt.u32.u64 %0, t; }"
        : "=r"(a) : "l"(p));
    return a;
}
__device__ __forceinline__ void cp_async16(uint32_t dst, const void* src) {
    asm volatile("cp.async.cg.shared.global [%0], [%1], 16;"
                 :: "r"(dst), "l"(src) : "memory");
}
__device__ __forceinline__ void cp_async_wait_all() {
    asm volatile("cp.async.commit_group;\n\tcp.async.wait_group 0;" ::: "memory");
}

// ---------------------------------------------------------------------------
// prep_kernel (fused): blocks [0, pb_blocks) build B rows (32 verts/block);
// blocks [pb_blocks, ...) run FK for 4 batches each + emit A rows (fp16).
// ---------------------------------------------------------------------------
#define PB_VPB 32     // vertices per prep-B block

__global__ __launch_bounds__(256)
void prep_kernel(const float* __restrict__ pose,
                 const float* __restrict__ J_hat,
                 const float* __restrict__ trans,
                 const float* __restrict__ T_hat,
                 const float* __restrict__ W,
                 int B, int V, int vpad, int rows_pad, int pb_blocks) {
    int tid = threadIdx.x;

    if ((int)blockIdx.x < pb_blocks) {
        // ---- B operand: m[v][k] = k<96 ? w[v][k/4]*vh[v][k%4] : (k==96 ? 1 : 0)
        int v_off = tid >> 7;            // 0..1
        int k = tid & 127;
        int j = k >> 2, y = k & 3;
        #pragma unroll
        for (int it = 0; it < PB_VPB / 2; it++) {
            int v = blockIdx.x * PB_VPB + it * 2 + v_off;
            if (v >= vpad) break;
            float val = 0.0f;
            if (v < V) {
                if (k < 96) {
                    float vh = (y < 3) ? T_hat[v * 3 + y] : 1.0f;
                    val = W[(size_t)v * NJ + j] * vh;
                } else if (k == KREAL - 1) {
                    val = 1.0f;
                }
            }
            g_Bm[(size_t)v * KTOT + k] = __float2half(val);
        }
        return;
    }

    // ---- A operand: FK for 4 batches, then emit rows 3b+x (fp16, K=97+pad)
    int blk = blockIdx.x - pb_blocks;
    __shared__ float Gs[4][NJ][GROW];
    int lb = tid / NJ;                   // local batch 0..3 (tid<96)
    int jj = tid - lb * NJ;
    bool jact = (tid < 96);
    int b = blk * 4 + lb;
    bool bok = jact && (b < B);

    if (bok) {
        float rx = pose[b * POSE_STRIDE + jj * 3 + 0];
        float ry = pose[b * POSE_STRIDE + jj * 3 + 1];
        float rz = pose[b * POSE_STRIDE + jj * 3 + 2];
        float theta = sqrtf(rx * rx + ry * ry + rz * rz) + 1e-8f;
        float inv = 1.0f / theta;
        float ux = rx * inv, uy = ry * inv, uz = rz * inv;
        float c = cosf(theta), s = sinf(theta), ic = 1.0f - c;
        int p = c_par[jj];
        float jx = J_hat[jj * 3 + 0], jy = J_hat[jj * 3 + 1], jz = J_hat[jj * 3 + 2];
        if (p >= 0) { jx -= J_hat[p*3+0]; jy -= J_hat[p*3+1]; jz -= J_hat[p*3+2]; }
        float* G = Gs[lb][jj];
        G[0] = c + ic*ux*ux;  G[1] = ic*ux*uy - s*uz; G[2]  = ic*ux*uz + s*uy; G[3]  = jx;
        G[4] = ic*uy*ux+s*uz; G[5] = c + ic*uy*uy;    G[6]  = ic*uy*uz - s*ux; G[7]  = jy;
        G[8] = ic*uz*ux-s*uy; G[9] = ic*uz*uy + s*ux; G[10] = c + ic*uz*uz;    G[11] = jz;
    }
    __syncthreads();

    int mylvl = jact ? c_lvl[jj] : -1;
    int myp = jact ? c_par[jj] : 0;
    #pragma unroll
    for (int lv = 1; lv <= 8; lv++) {
        float tmp[GROW];
        bool act = bok && (mylvl == lv);
        if (act) {
            const float* P = Gs[lb][myp];
            const float* L = Gs[lb][jj];
            #pragma unroll
            for (int x = 0; x < 3; x++) {
                float p0 = P[x*4+0], p1 = P[x*4+1], p2 = P[x*4+2], p3 = P[x*4+3];
                tmp[x*4+0] = p0*L[0] + p1*L[4] + p2*L[8];
                tmp[x*4+1] = p0*L[1] + p1*L[5] + p2*L[9];
                tmp[x*4+2] = p0*L[2] + p1*L[6] + p2*L[10];
                tmp[x*4+3] = p0*L[3] + p1*L[7] + p2*L[11] + p3;
            }
        }
        __syncthreads();
        if (act) {
            #pragma unroll
            for (int k = 0; k < GROW; k++) Gs[lb][jj][k] = tmp[k];
        }
        __syncthreads();
    }

    if (bok) {
        float jx = J_hat[jj*3+0], jy = J_hat[jj*3+1], jz = J_hat[jj*3+2];
        float* G = Gs[lb][jj];
        G[3]  -= G[0]*jx + G[1]*jy + G[2]*jz;
        G[7]  -= G[4]*jx + G[5]*jy + G[6]*jz;
        G[11] -= G[8]*jx + G[9]*jy + G[10]*jz;
    }
    __syncthreads();

    // emit: 4 batches x 3 rows x 128 cols = 1536 fp16 over 256 threads
    #pragma unroll
    for (int it = 0; it < 6; it++) {
        int idx = it * 256 + tid;        // 0..1535
        int k = idx & 127;
        int rl = idx >> 7;               // 0..11 = lb*3 + x
        int elb = rl >> 2;               // careful: rl in 0..11 -> lb = rl/3
        elb = rl / 3;
        int x = rl - elb * 3;
        int eb = blk * 4 + elb;
        int row = eb * 3 + x;
        if (row >= rows_pad) continue;
        float val = 0.0f;
        if (eb < B) {
            if (k < 96) {
                val = Gs[elb][k >> 2][x * 4 + (k & 3)];
            } else if (k == KREAL - 1) {
                val = trans[eb * 3 + x];
            }
        }
        g_A[(size_t)row * KTOT + k] = __float2half(val);
    }
}

// ---------------------------------------------------------------------------
// GEMM via wmma fp16 (single pass, K=128), SMEM-staged KC=64 chunks.
// CTA tile 128 rows x 128 verts; 8 warps (4 row x 2 col), warp tile 32x64.
// ---------------------------------------------------------------------------
#define LDC 68     // epilogue stage: 128 x (64+4) floats

__global__ __launch_bounds__(256)
void gemm_kernel(float* __restrict__ out, int V, int B) {
    __shared__ __align__(16) char smbuf[2 * 128 * LDS * 2];  // 36.9 KB
    __half* sA = reinterpret_cast<__half*>(smbuf);
    __half* sB = sA + 128 * LDS;
    float* sepi = reinterpret_cast<float*>(smbuf);

    int tid = threadIdx.x;
    int warp = tid >> 5;
    int wr = warp >> 1;
    int wc = warp & 1;
    int r0 = blockIdx.x * 128;
    int v0 = blockIdx.y * 128;
    int M = 3 * B;

    wmma::fragment<wmma::accumulator, 16, 16, 16, float> acc[2][4];
    #pragma unroll
    for (int i = 0; i < 2; i++)
        #pragma unroll
        for (int j = 0; j < 4; j++)
            wmma::fill_fragment(acc[i][j], 0.0f);

    uint32_t sA32 = smem_u32(sA);
    uint32_t sB32 = smem_u32(sB);

    for (int c = 0; c < NCHUNK; c++) {
        #pragma unroll
        for (int p = 0; p < 4; p++) {
            int idx = p * 256 + tid;             // 0..1023
            int row = idx >> 3, seg = idx & 7;   // 8 segs x 16B = 64 fp16
            uint32_t soff = (uint32_t)(row * LDS + seg * 8) * 2;
            cp_async16(sA32 + soff,
                       g_A + (size_t)(r0 + row) * KTOT + c * KC + seg * 8);
            cp_async16(sB32 + soff,
                       g_Bm + (size_t)(v0 + row) * KTOT + c * KC + seg * 8);
        }
        cp_async_wait_all();
        __syncthreads();

        #pragma unroll
        for (int ks = 0; ks < KC / 16; ks++) {
            int kk = ks * 16;
            wmma::fragment<wmma::matrix_a, 16, 16, 16, __half, wmma::row_major> af[2];
            wmma::fragment<wmma::matrix_b, 16, 16, 16, __half, wmma::col_major> bf[4];
            #pragma unroll
            for (int i = 0; i < 2; i++)
                wmma::load_matrix_sync(af[i], sA + (wr * 32 + i * 16) * LDS + kk, LDS);
            #pragma unroll
            for (int j = 0; j < 4; j++)
                wmma::load_matrix_sync(bf[j], sB + (wc * 64 + j * 16) * LDS + kk, LDS);
            #pragma unroll
            for (int i = 0; i < 2; i++)
                #pragma unroll
                for (int j = 0; j < 4; j++)
                    wmma::mma_sync(acc[i][j], af[i], bf[j], acc[i][j]);
        }
        __syncthreads();
    }

    // Epilogue: two passes (col-warp halves) through SMEM; row -> (b, x) by /3.
    for (int p = 0; p < 2; p++) {
        __syncthreads();
        if (wc == p) {
            #pragma unroll
            for (int i = 0; i < 2; i++)
                #pragma unroll
                for (int j = 0; j < 4; j++)
                    wmma::store_matrix_sync(sepi + (wr * 32 + i * 16) * LDC + j * 16,
                                            acc[i][j], LDC, wmma::mem_row_major);
        }
        __syncthreads();

        #pragma unroll 4
        for (int idx = tid; idx < 128 * 64; idx += 256) {
            int row = idx >> 6;
            int vl = idx & 63;
            int gr = r0 + row;
            int v = v0 + p * 64 + vl;
            if (gr < M && v < V) {
                int b = gr / 3;
                int x = gr - 3 * b;
                out[((size_t)b * V + v) * 3 + x] = sepi[row * LDC + vl];
            }
        }
    }
}

// ---------------------------------------------------------------------------
// Launch: pure kernel launches only (graph-capture safe).
// ---------------------------------------------------------------------------
extern "C" void kernel_launch(void* const* d_in, const int* in_sizes, int n_in,
                              void* d_out, int out_size) {
    const float* T_hat   = (const float*)d_in[0];   // (V,3)
    const float* J_hat   = (const float*)d_in[1];   // (24,3)
    const float* weights = (const float*)d_in[2];   // (V,24)
    const float* pose    = (const float*)d_in[3];   // (B,72)
    const float* trans   = (const float*)d_in[4];   // (B,3)
    float* out = (float*)d_out;

    int V = in_sizes[0] / 3;
    int B = in_sizes[3] / POSE_STRIDE;
    if (B > MAX_B) B = MAX_B;

    int rows_pad = ((3 * B + 127) / 128) * 128;     // 1536 for B=512 (exact)
    int vpad = ((V + 127) / 128) * 128;             // 6912 for V=6890
    if (rows_pad > MAX_ROWS) rows_pad = MAX_ROWS;
    if (vpad > MAX_VPAD) vpad = MAX_VPAD;

    int pb_blocks = (vpad + PB_VPB - 1) / PB_VPB;           // 216
    int nbat_pad = (rows_pad + 2) / 3;
    int fk_blocks = (nbat_pad + 3) / 4;                      // 128
    prep_kernel<<<pb_blocks + fk_blocks, 256>>>(pose, J_hat, trans, T_hat,
                                                weights, B, V, vpad, rows_pad,
                                                pb_blocks);

    dim3 grid(rows_pad / 128, vpad / 128);
    gemm_kernel<<<grid, 256>>>(out, V, B);
}